// round 2
// baseline (speedup 1.0000x reference)
#include <cuda_runtime.h>
#include <cstdint>

// Problem constants (fixed by the reference):
//   L = 256 bitstream length, H = W = 512
// Inputs (metadata order):
//   d_in[0] = src_ns      [512*512] f32
//   d_in[1] = src_st      [512*512] f32
//   d_in[2] = new_ns_len  [512*512] f32 (integer-valued, in [0,256])
//   d_in[3] = rng         [256]     f32
// Output: [256, 512, 512] f32 bitstream (0.0 / 1.0)

#define L_BITS 256
#define HW     (512 * 512)
#define PIX4   (HW / 4)      // 65536 float4 pixel groups

__global__ __launch_bounds__(256, 8)
void nsbuilder_kernel(const float* __restrict__ src_ns,
                      const float* __restrict__ src_st,
                      const float* __restrict__ nnl,
                      const float* __restrict__ rng,
                      float* __restrict__ out)
{
    __shared__ float s_rng[L_BITS];
    const int tid = threadIdx.x;
    // 256 threads per block: one element each
    s_rng[tid] = rng[tid];
    __syncthreads();

    const int g = blockIdx.x * blockDim.x + tid;   // float4 group id, < PIX4
    const float4 ns4 = reinterpret_cast<const float4*>(src_ns)[g];
    const float4 st4 = reinterpret_cast<const float4*>(src_st)[g];
    const float4 nl4 = reinterpret_cast<const float4*>(nnl)[g];

    const float ns[4] = {ns4.x, ns4.y, ns4.z, ns4.w};
    const float st[4] = {st4.x, st4.y, st4.z, st4.w};
    const int   nl[4] = {(int)nl4.x, (int)nl4.y, (int)nl4.z, (int)nl4.w};

    float4* o = reinterpret_cast<float4*>(out) + g;
    const int stride4 = HW / 4;  // float4 stride between consecutive t-planes

    #pragma unroll 4
    for (int t = 0; t < L_BITS; ++t) {
        const float rt = s_rng[t];   // uniform broadcast
        float v[4];
        #pragma unroll
        for (int j = 0; j < 4; ++j) {
            const bool is_ns = (t < nl[j]);
            // stable-phase rng index; only meaningful when !is_ns, clamp for safety
            int idx = t - nl[j];
            idx = idx < 0 ? 0 : (idx > L_BITS - 1 ? L_BITS - 1 : idx);
            const float r   = is_ns ? rt    : s_rng[idx];
            const float thr = is_ns ? ns[j] : st[j];
            v[j] = (thr > r) ? 1.0f : 0.0f;
        }
        o[(size_t)t * stride4] = make_float4(v[0], v[1], v[2], v[3]);
    }
}

extern "C" void kernel_launch(void* const* d_in, const int* in_sizes, int n_in,
                              void* d_out, int out_size)
{
    const float* src_ns = (const float*)d_in[0];
    const float* src_st = (const float*)d_in[1];
    const float* nnl    = (const float*)d_in[2];
    const float* rng    = (const float*)d_in[3];
    float* out = (float*)d_out;

    // PIX4 = 65536 groups, 256 threads/block -> 256 blocks
    nsbuilder_kernel<<<PIX4 / 256, 256>>>(src_ns, src_st, nnl, rng, out);
}